// round 11
// baseline (speedup 1.0000x reference)
#include <cuda_runtime.h>
#include <math.h>
#include <stdint.h>

#define NPTS   (1 << 20)
#define RESG   160
#define TILE   64
#define NTILES (NPTS / TILE)
#define THREADS 512

#define ST   136   // h / W2t stride: LDS.64 bank-pair conflict-free
#define SRF  56    // rf stride: LDS.64 bank-pair conflict-free

// ---- smem float offsets ----
#define F_DW2T 0                        // 128*136
#define F_RW2T 17408
#define F_HD   34816                    // 64*136
#define F_HR   43520
#define F_RF   52224                    // 64*56
#define F_DB1  55808
#define F_DB2  55936
#define F_RB1  56064
#define F_RB2  56192
#define F_DW3  56320
#define F_RW3  56448                    // [3][128]
#define F_DB3  56832
#define F_RB3  56833                    // 3
#define F_PD   56840                    // [4][64]
#define F_PR   57096                    // [3][4][64]
#define SMEM_FLOATS 57864
#define SMEM_BYTES  (SMEM_FLOATS * 4)

#define BARC(id)  asm volatile("bar.sync %0, 256;" :: "r"(id) : "memory")

__device__ __forceinline__ int pc8(int c) {   // pair-interleave k within 8-group
    return (c & ~7) | ((c & 3) << 1) | ((c >> 2) & 1);
}

__device__ __forceinline__ float rtf32(float f) {
    uint32_t u;
    asm("cvt.rna.tf32.f32 %0, %1;" : "=r"(u) : "f"(f));
    return __uint_as_float(u);
}

__device__ __forceinline__ void mma8(float c[4], const uint32_t a[4],
                                     uint32_t b0, uint32_t b1) {
    asm volatile(
        "mma.sync.aligned.m16n8k8.row.col.f32.tf32.tf32.f32 "
        "{%0,%1,%2,%3}, {%4,%5,%6,%7}, {%8,%9}, {%0,%1,%2,%3};"
        : "+f"(c[0]), "+f"(c[1]), "+f"(c[2]), "+f"(c[3])
        : "r"(a[0]), "r"(a[1]), "r"(a[2]), "r"(a[3]), "r"(b0), "r"(b1));
}

// featurize: 8 threads/point, 512 threads -> 64 points, writes permuted rf
__device__ __forceinline__ void featurize(float* __restrict__ sm,
                                          const float* __restrict__ x,
                                          const float* __restrict__ grid,
                                          int base, int tid) {
    const int p = tid >> 3, corner = tid & 7;
    const float* xp = x + (size_t)(base + p) * 8;
    float px = fminf(fmaxf(xp[0], 0.f), 1.f);
    float py = fminf(fmaxf(xp[1], 0.f), 1.f);
    float pz = fminf(fmaxf(xp[2], 0.f), 1.f);
    float fx = px * 159.f, fy = py * 159.f, fz = pz * 159.f;
    float x0f = fminf(floorf(fx), 158.f);
    float y0f = fminf(floorf(fy), 158.f);
    float z0f = fminf(floorf(fz), 158.f);
    float wx = fx - x0f, wy = fy - y0f, wz = fz - z0f;
    int xi = (int)x0f + ((corner >> 2) & 1);
    int yi = (int)y0f + ((corner >> 1) & 1);
    int zi = (int)z0f + (corner & 1);
    float wgt = ((corner & 4) ? wx : 1.f - wx) *
                ((corner & 2) ? wy : 1.f - wy) *
                ((corner & 1) ? wz : 1.f - wz);
    const float* gp = grid + (size_t)((xi * RESG + yi) * RESG + zi) * 12;
    float4 g0 = *(const float4*)gp;
    float4 g1 = *(const float4*)(gp + 4);
    float4 g2 = *(const float4*)(gp + 8);
    float gv[12] = {g0.x, g0.y, g0.z, g0.w, g1.x, g1.y, g1.z, g1.w,
                    g2.x, g2.y, g2.z, g2.w};
#pragma unroll
    for (int c = 0; c < 12; c++) gv[c] *= wgt;
#pragma unroll
    for (int off = 4; off; off >>= 1)
#pragma unroll
        for (int c = 0; c < 12; c++)
            gv[c] += __shfl_down_sync(0xffffffffu, gv[c], off);
    float* rp = sm + F_RF + p * SRF;
    if (corner == 0) {
#pragma unroll
        for (int c = 0; c < 12; c++) rp[pc8(c)] = rtf32(gv[c]);
    } else if (corner <= 3) {
        int d = corner - 1;
        float vv = xp[5 + d];
        rp[pc8(12 + d)] = rtf32(vv);
        float f = 1.f;
#pragma unroll
        for (int k = 0; k < 4; k++) {
            rp[pc8(15 + 6 * k + d)]     = rtf32(sinf(vv * f));
            rp[pc8(15 + 6 * k + 3 + d)] = rtf32(cosf(vv * f));
            f *= 2.f;
        }
    } else if (corner == 4) {
        rp[pc8(39)] = rtf32(xp[3]);
        rp[pc8(40)] = rtf32(xp[4]);
    }
}

__global__ void __launch_bounds__(THREADS, 1) fastsurf_ws2(
    const float* __restrict__ x, const float* __restrict__ grid,
    const float* __restrict__ dW1, const float* __restrict__ db1,
    const float* __restrict__ dW2, const float* __restrict__ db2,
    const float* __restrict__ dW3, const float* __restrict__ db3,
    const float* __restrict__ rW1, const float* __restrict__ rb1,
    const float* __restrict__ rW2, const float* __restrict__ rb2,
    const float* __restrict__ rW3, const float* __restrict__ rb3,
    float* __restrict__ out) {
    extern __shared__ float sm[];
    const int tid = threadIdx.x;

    // ---- one-time staging (k-permuted, tf32-rounded) ----
    for (int i = tid; i < 16384; i += THREADS) {
        int k = i >> 7, n = i & 127;
        sm[F_DW2T + n * ST + pc8(k)] = rtf32(dW2[i]);
        sm[F_RW2T + n * ST + pc8(k)] = rtf32(rW2[i]);
    }
    if (tid < 128) {
        sm[F_DB1 + tid] = db1[tid];
        sm[F_DB2 + tid] = db2[tid];
        sm[F_RB1 + tid] = rb1[tid];
        sm[F_RB2 + tid] = rb2[tid];
        sm[F_DW3 + tid] = dW3[tid];
        sm[F_RW3 + 0 * 128 + tid] = rW3[tid * 3 + 0];
        sm[F_RW3 + 1 * 128 + tid] = rW3[tid * 3 + 1];
        sm[F_RW3 + 2 * 128 + tid] = rW3[tid * 3 + 2];
    }
    if (tid == 0) sm[F_DB3] = db3[0];
    if (tid < 3) sm[F_RB3 + tid] = rb3[tid];
    // zero rf pad: physical cols 41..47 (bijection of logical 41..47)
    for (int i = tid; i < 64 * 7; i += THREADS) {
        int row = i / 7, c = 41 + i % 7;
        sm[F_RF + row * SRF + c] = 0.f;
    }
    __syncthreads();

    const int lane = tid & 31, warp = tid >> 5;
    const int chain = warp >> 3;          // 0 = density, 1 = rgb
    const int cw = warp & 7;
    const int mi = cw & 1, ni = cw >> 1;  // m 2 x n 4
    const int m0 = mi * 32, n0 = ni * 32;
    const int r = lane >> 2, q = lane & 3;
    const int tloc = tid & 255;

    if (chain == 0) {
        // ================= DENSITY =================
        for (int tile = blockIdx.x; tile < NTILES; tile += gridDim.x) {
            const int base = tile * TILE;
            featurize(sm, x, grid, base, tid);
            __syncthreads();

            // L1 weight frags from gmem (L1-cached, same addrs every tile)
            uint32_t wb[2][4][2];
#pragma unroll
            for (int ks = 0; ks < 2; ks++)
#pragma unroll
                for (int f = 0; f < 4; f++)
#pragma unroll
                    for (int j = 0; j < 2; j++) {
                        int k = 8 * ks + q + 4 * j, n = n0 + f * 8 + r;
                        wb[ks][f][j] = (k < 12) ? __float_as_uint(rtf32(dW1[k * 128 + n])) : 0u;
                    }
            float c[2][4][4];
#pragma unroll
            for (int mb = 0; mb < 2; mb++)
#pragma unroll
                for (int f = 0; f < 4; f++)
                    c[mb][f][0] = c[mb][f][1] = c[mb][f][2] = c[mb][f][3] = 0.f;
            const float* ap = sm + F_RF + (m0 + r) * SRF + 2 * q;
#pragma unroll
            for (int ks = 0; ks < 2; ks++) {
                uint32_t a[2][4];
#pragma unroll
                for (int mb = 0; mb < 2; mb++) {
                    float2 lo = *(const float2*)(ap + mb * 16 * SRF + 8 * ks);
                    float2 hi = *(const float2*)(ap + mb * 16 * SRF + 8 * SRF + 8 * ks);
                    a[mb][0] = __float_as_uint(lo.x); a[mb][1] = __float_as_uint(hi.x);
                    a[mb][2] = __float_as_uint(lo.y); a[mb][3] = __float_as_uint(hi.y);
                }
#pragma unroll
                for (int f = 0; f < 4; f++)
#pragma unroll
                    for (int mb = 0; mb < 2; mb++)
                        mma8(c[mb][f], a[mb], wb[ks][f][0], wb[ks][f][1]);
            }
            // epilogue -> HD (permuted cols)
#pragma unroll
            for (int f = 0; f < 4; f++) {
                int lc = n0 + f * 8 + 2 * q;
                float2 b = *(const float2*)(sm + F_DB1 + lc);
                int c0p = pc8(lc), c1p = pc8(lc + 1);
#pragma unroll
                for (int mb = 0; mb < 2; mb++) {
                    float* hp = sm + F_HD + (m0 + mb * 16 + r) * ST;
                    hp[c0p] = rtf32(fmaxf(c[mb][f][0] + b.x, 0.f));
                    hp[c1p] = rtf32(fmaxf(c[mb][f][1] + b.y, 0.f));
                    hp[8 * ST + c0p] = rtf32(fmaxf(c[mb][f][2] + b.x, 0.f));
                    hp[8 * ST + c1p] = rtf32(fmaxf(c[mb][f][3] + b.y, 0.f));
                }
            }
            BARC(1);

            // L2: HD(K128) x dW2
#pragma unroll
            for (int mb = 0; mb < 2; mb++)
#pragma unroll
                for (int f = 0; f < 4; f++)
                    c[mb][f][0] = c[mb][f][1] = c[mb][f][2] = c[mb][f][3] = 0.f;
            const float* hp0 = sm + F_HD + (m0 + r) * ST + 2 * q;
            const float* wp0 = sm + F_DW2T + (n0 + r) * ST + 2 * q;
#pragma unroll
            for (int ks = 0; ks < 16; ks++) {
                uint32_t b[4][2];
#pragma unroll
                for (int f = 0; f < 4; f++) {
                    float2 bb = *(const float2*)(wp0 + f * 8 * ST + 8 * ks);
                    b[f][0] = __float_as_uint(bb.x);
                    b[f][1] = __float_as_uint(bb.y);
                }
                uint32_t a[2][4];
#pragma unroll
                for (int mb = 0; mb < 2; mb++) {
                    float2 lo = *(const float2*)(hp0 + mb * 16 * ST + 8 * ks);
                    float2 hi = *(const float2*)(hp0 + mb * 16 * ST + 8 * ST + 8 * ks);
                    a[mb][0] = __float_as_uint(lo.x); a[mb][1] = __float_as_uint(hi.x);
                    a[mb][2] = __float_as_uint(lo.y); a[mb][3] = __float_as_uint(hi.y);
                }
#pragma unroll
                for (int f = 0; f < 4; f++)
#pragma unroll
                    for (int mb = 0; mb < 2; mb++)
                        mma8(c[mb][f], a[mb], b[f][0], b[f][1]);
            }
            // fused sdf head
            float ps[2][2] = {{0.f, 0.f}, {0.f, 0.f}};
#pragma unroll
            for (int f = 0; f < 4; f++) {
                int lc = n0 + f * 8 + 2 * q;
                float2 b2 = *(const float2*)(sm + F_DB2 + lc);
                float2 w3 = *(const float2*)(sm + F_DW3 + lc);
#pragma unroll
                for (int mb = 0; mb < 2; mb++) {
                    ps[mb][0] = fmaf(fmaxf(c[mb][f][0] + b2.x, 0.f), w3.x,
                                fmaf(fmaxf(c[mb][f][1] + b2.y, 0.f), w3.y, ps[mb][0]));
                    ps[mb][1] = fmaf(fmaxf(c[mb][f][2] + b2.x, 0.f), w3.x,
                                fmaf(fmaxf(c[mb][f][3] + b2.y, 0.f), w3.y, ps[mb][1]));
                }
            }
#pragma unroll
            for (int mb = 0; mb < 2; mb++)
#pragma unroll
                for (int hh = 0; hh < 2; hh++) {
                    ps[mb][hh] += __shfl_xor_sync(0xffffffffu, ps[mb][hh], 1);
                    ps[mb][hh] += __shfl_xor_sync(0xffffffffu, ps[mb][hh], 2);
                }
            if (q == 0) {
#pragma unroll
                for (int mb = 0; mb < 2; mb++) {
                    sm[F_PD + ni * 64 + m0 + mb * 16 + r]     = ps[mb][0];
                    sm[F_PD + ni * 64 + m0 + mb * 16 + r + 8] = ps[mb][1];
                }
            }
            BARC(1);
            if (tloc < 64)
                out[(size_t)(base + tloc) * 4 + 3] =
                    sm[F_PD + tloc] + sm[F_PD + 64 + tloc] +
                    sm[F_PD + 128 + tloc] + sm[F_PD + 192 + tloc] + sm[F_DB3];
            __syncthreads();
        }
    } else {
        // ================= RGB =================
        for (int tile = blockIdx.x; tile < NTILES; tile += gridDim.x) {
            const int base = tile * TILE;
            featurize(sm, x, grid, base, tid);
            __syncthreads();

            uint32_t wb[6][4][2];
#pragma unroll
            for (int ks = 0; ks < 6; ks++)
#pragma unroll
                for (int f = 0; f < 4; f++)
#pragma unroll
                    for (int j = 0; j < 2; j++) {
                        int k = 8 * ks + q + 4 * j, n = n0 + f * 8 + r;
                        wb[ks][f][j] = (k < 41) ? __float_as_uint(rtf32(rW1[k * 128 + n])) : 0u;
                    }
            float c[2][4][4];
#pragma unroll
            for (int mb = 0; mb < 2; mb++)
#pragma unroll
                for (int f = 0; f < 4; f++)
                    c[mb][f][0] = c[mb][f][1] = c[mb][f][2] = c[mb][f][3] = 0.f;
            const float* ap = sm + F_RF + (m0 + r) * SRF + 2 * q;
#pragma unroll
            for (int ks = 0; ks < 6; ks++) {
                uint32_t a[2][4];
#pragma unroll
                for (int mb = 0; mb < 2; mb++) {
                    float2 lo = *(const float2*)(ap + mb * 16 * SRF + 8 * ks);
                    float2 hi = *(const float2*)(ap + mb * 16 * SRF + 8 * SRF + 8 * ks);
                    a[mb][0] = __float_as_uint(lo.x); a[mb][1] = __float_as_uint(hi.x);
                    a[mb][2] = __float_as_uint(lo.y); a[mb][3] = __float_as_uint(hi.y);
                }
#pragma unroll
                for (int f = 0; f < 4; f++)
#pragma unroll
                    for (int mb = 0; mb < 2; mb++)
                        mma8(c[mb][f], a[mb], wb[ks][f][0], wb[ks][f][1]);
            }
#pragma unroll
            for (int f = 0; f < 4; f++) {
                int lc = n0 + f * 8 + 2 * q;
                float2 b = *(const float2*)(sm + F_RB1 + lc);
                int c0p = pc8(lc), c1p = pc8(lc + 1);
#pragma unroll
                for (int mb = 0; mb < 2; mb++) {
                    float* hp = sm + F_HR + (m0 + mb * 16 + r) * ST;
                    hp[c0p] = rtf32(fmaxf(c[mb][f][0] + b.x, 0.f));
                    hp[c1p] = rtf32(fmaxf(c[mb][f][1] + b.y, 0.f));
                    hp[8 * ST + c0p] = rtf32(fmaxf(c[mb][f][2] + b.x, 0.f));
                    hp[8 * ST + c1p] = rtf32(fmaxf(c[mb][f][3] + b.y, 0.f));
                }
            }
            BARC(2);

#pragma unroll
            for (int mb = 0; mb < 2; mb++)
#pragma unroll
                for (int f = 0; f < 4; f++)
                    c[mb][f][0] = c[mb][f][1] = c[mb][f][2] = c[mb][f][3] = 0.f;
            const float* hp0 = sm + F_HR + (m0 + r) * ST + 2 * q;
            const float* wp0 = sm + F_RW2T + (n0 + r) * ST + 2 * q;
#pragma unroll
            for (int ks = 0; ks < 16; ks++) {
                uint32_t b[4][2];
#pragma unroll
                for (int f = 0; f < 4; f++) {
                    float2 bb = *(const float2*)(wp0 + f * 8 * ST + 8 * ks);
                    b[f][0] = __float_as_uint(bb.x);
                    b[f][1] = __float_as_uint(bb.y);
                }
                uint32_t a[2][4];
#pragma unroll
                for (int mb = 0; mb < 2; mb++) {
                    float2 lo = *(const float2*)(hp0 + mb * 16 * ST + 8 * ks);
                    float2 hi = *(const float2*)(hp0 + mb * 16 * ST + 8 * ST + 8 * ks);
                    a[mb][0] = __float_as_uint(lo.x); a[mb][1] = __float_as_uint(hi.x);
                    a[mb][2] = __float_as_uint(lo.y); a[mb][3] = __float_as_uint(hi.y);
                }
#pragma unroll
                for (int f = 0; f < 4; f++)
#pragma unroll
                    for (int mb = 0; mb < 2; mb++)
                        mma8(c[mb][f], a[mb], b[f][0], b[f][1]);
            }
            // fused rgb head
            float pc[3][2][2];
#pragma unroll
            for (int ch = 0; ch < 3; ch++)
#pragma unroll
                for (int mb = 0; mb < 2; mb++)
                    pc[ch][mb][0] = pc[ch][mb][1] = 0.f;
#pragma unroll
            for (int f = 0; f < 4; f++) {
                int lc = n0 + f * 8 + 2 * q;
                float2 b2 = *(const float2*)(sm + F_RB2 + lc);
#pragma unroll
                for (int mb = 0; mb < 2; mb++) {
                    float h0 = fmaxf(c[mb][f][0] + b2.x, 0.f);
                    float h1 = fmaxf(c[mb][f][1] + b2.y, 0.f);
                    float h2 = fmaxf(c[mb][f][2] + b2.x, 0.f);
                    float h3 = fmaxf(c[mb][f][3] + b2.y, 0.f);
#pragma unroll
                    for (int ch = 0; ch < 3; ch++) {
                        float2 w3 = *(const float2*)(sm + F_RW3 + ch * 128 + lc);
                        pc[ch][mb][0] = fmaf(h0, w3.x, fmaf(h1, w3.y, pc[ch][mb][0]));
                        pc[ch][mb][1] = fmaf(h2, w3.x, fmaf(h3, w3.y, pc[ch][mb][1]));
                    }
                }
            }
#pragma unroll
            for (int ch = 0; ch < 3; ch++)
#pragma unroll
                for (int mb = 0; mb < 2; mb++)
#pragma unroll
                    for (int hh = 0; hh < 2; hh++) {
                        pc[ch][mb][hh] += __shfl_xor_sync(0xffffffffu, pc[ch][mb][hh], 1);
                        pc[ch][mb][hh] += __shfl_xor_sync(0xffffffffu, pc[ch][mb][hh], 2);
                    }
            if (q == 0) {
#pragma unroll
                for (int ch = 0; ch < 3; ch++)
#pragma unroll
                    for (int mb = 0; mb < 2; mb++) {
                        sm[F_PR + ch * 256 + ni * 64 + m0 + mb * 16 + r]     = pc[ch][mb][0];
                        sm[F_PR + ch * 256 + ni * 64 + m0 + mb * 16 + r + 8] = pc[ch][mb][1];
                    }
            }
            BARC(2);
            if (tloc < 64) {
#pragma unroll
                for (int ch = 0; ch < 3; ch++)
                    out[(size_t)(base + tloc) * 4 + ch] =
                        sm[F_PR + ch * 256 + tloc] + sm[F_PR + ch * 256 + 64 + tloc] +
                        sm[F_PR + ch * 256 + 128 + tloc] + sm[F_PR + ch * 256 + 192 + tloc] +
                        sm[F_RB3 + ch];
            }
            __syncthreads();
        }
    }
}

extern "C" void kernel_launch(void* const* d_in, const int* in_sizes, int n_in,
                              void* d_out, int out_size) {
    (void)in_sizes; (void)n_in; (void)out_size;
    const float* x    = (const float*)d_in[0];
    const float* grid = (const float*)d_in[1];
    const float* dW1  = (const float*)d_in[2];
    const float* db1  = (const float*)d_in[3];
    const float* dW2  = (const float*)d_in[4];
    const float* db2  = (const float*)d_in[5];
    const float* dW3  = (const float*)d_in[6];
    const float* db3  = (const float*)d_in[7];
    const float* rW1  = (const float*)d_in[8];
    const float* rb1  = (const float*)d_in[9];
    const float* rW2  = (const float*)d_in[10];
    const float* rb2  = (const float*)d_in[11];
    const float* rW3  = (const float*)d_in[12];
    const float* rb3  = (const float*)d_in[13];
    float* out = (float*)d_out;

    int nsm = 148;
    cudaDeviceGetAttribute(&nsm, cudaDevAttrMultiProcessorCount, 0);
    cudaFuncSetAttribute(fastsurf_ws2,
                         cudaFuncAttributeMaxDynamicSharedMemorySize, SMEM_BYTES);
    fastsurf_ws2<<<nsm, THREADS, SMEM_BYTES>>>(x, grid, dW1, db1, dW2, db2, dW3, db3,
                                               rW1, rb1, rW2, rb2, rW3, rb3, out);
}

// round 14
// speedup vs baseline: 1.7237x; 1.7237x over previous
#include <cuda_runtime.h>
#include <cuda_fp16.h>
#include <math.h>
#include <stdint.h>

#define NPTS   (1 << 20)
#define RESG   160
#define TILE   64
#define NTILES (NPTS / TILE)
#define THREADS 512

#define RW2 64   // u32 per row for W2/h (K=128 halves = 64 u32)
#define RRF 32   // u32 per row for rf  (K=64 halves = 32 u32)

// ---- u32 offsets in shared ----
#define U_DW2T 0
#define U_RW2T 8192
#define U_HD   16384
#define U_HR   20480
#define U_RF   24576
#define F_DB1  26624
#define F_DB2  (F_DB1 + 128)
#define F_RB1  (F_DB2 + 128)
#define F_RB2  (F_RB1 + 128)
#define F_DW3  (F_RB2 + 128)
#define F_RW3  (F_DW3 + 128)    // [3][128]
#define F_DB3  (F_RW3 + 384)
#define F_RB3  (F_DB3 + 1)      // 3
#define F_PD   (F_RB3 + 3)      // [4][64]
#define F_PR   (F_PD + 256)     // [3][4][64]
#define SMEM_U32   (F_PR + 768)
#define SMEM_BYTES (SMEM_U32 * 4)

#define BARC(id) asm volatile("bar.sync %0, 256;" :: "r"(id) : "memory")

// physical u32 slot within a row: 16-u32 groups, pc16 interleave + row-parity xor
__device__ __forceinline__ int physu(int j, int par) {
    return (((j >> 4) ^ par) << 4) | ((j & 3) << 2) | ((j >> 2) & 3);
}

__device__ __forceinline__ uint32_t packh2(float lo, float hi) {
    __half2 h = __floats2half2_rn(lo, hi);
    return *(uint32_t*)&h;
}

__device__ __forceinline__ void mma16(float c[4], uint32_t a0, uint32_t a1,
                                      uint32_t a2, uint32_t a3,
                                      uint32_t b0, uint32_t b1) {
    asm volatile(
        "mma.sync.aligned.m16n8k16.row.col.f32.f16.f16.f32 "
        "{%0,%1,%2,%3}, {%4,%5,%6,%7}, {%8,%9}, {%0,%1,%2,%3};"
        : "+f"(c[0]), "+f"(c[1]), "+f"(c[2]), "+f"(c[3])
        : "r"(a0), "r"(a1), "r"(a2), "r"(a3), "r"(b0), "r"(b1));
}

// featurize: 8 threads/point, 512 threads -> 64 points, fp16 packed rf
__device__ __forceinline__ void featurize(uint32_t* __restrict__ smu,
                                          const float* __restrict__ x,
                                          const float* __restrict__ grid,
                                          int base, int tid) {
    const int p = tid >> 3, corner = tid & 7;
    const float* xp = x + (size_t)(base + p) * 8;
    float px = fminf(fmaxf(xp[0], 0.f), 1.f);
    float py = fminf(fmaxf(xp[1], 0.f), 1.f);
    float pz = fminf(fmaxf(xp[2], 0.f), 1.f);
    float fx = px * 159.f, fy = py * 159.f, fz = pz * 159.f;
    float x0f = fminf(floorf(fx), 158.f);
    float y0f = fminf(floorf(fy), 158.f);
    float z0f = fminf(floorf(fz), 158.f);
    float wx = fx - x0f, wy = fy - y0f, wz = fz - z0f;
    int xi = (int)x0f + ((corner >> 2) & 1);
    int yi = (int)y0f + ((corner >> 1) & 1);
    int zi = (int)z0f + (corner & 1);
    float wgt = ((corner & 4) ? wx : 1.f - wx) *
                ((corner & 2) ? wy : 1.f - wy) *
                ((corner & 1) ? wz : 1.f - wz);
    const float* gp = grid + (size_t)((xi * RESG + yi) * RESG + zi) * 12;
    float4 g0 = *(const float4*)gp;
    float4 g1 = *(const float4*)(gp + 4);
    float4 g2 = *(const float4*)(gp + 8);
    float gv[12] = {g0.x, g0.y, g0.z, g0.w, g1.x, g1.y, g1.z, g1.w,
                    g2.x, g2.y, g2.z, g2.w};
#pragma unroll
    for (int c = 0; c < 12; c++) gv[c] *= wgt;
#pragma unroll
    for (int off = 4; off; off >>= 1)
#pragma unroll
        for (int c = 0; c < 12; c++)
            gv[c] += __shfl_down_sync(0xffffffffu, gv[c], off);
    __half* hsm = (__half*)smu;
    const int par = p & 1;
#define STH(kk, vv) do { int j_ = (kk) >> 1; \
        hsm[(U_RF + p * RRF + physu(j_, par)) * 2 + ((kk) & 1)] = __float2half_rn(vv); } while (0)
    if (corner == 0) {
#pragma unroll
        for (int c = 0; c < 12; c++) STH(c, gv[c]);
    } else if (corner <= 3) {
        int d = corner - 1;
        float vv = xp[5 + d];
        STH(12 + d, vv);
        float f = 1.f;
#pragma unroll
        for (int m = 0; m < 4; m++) {
            STH(15 + 6 * m + d, __sinf(vv * f));
            STH(15 + 6 * m + 3 + d, __cosf(vv * f));
            f *= 2.f;
        }
    } else if (corner == 4) {
        STH(39, xp[3]);
        STH(40, xp[4]);
    }
#undef STH
}

__global__ void __launch_bounds__(THREADS, 1) fastsurf_h16(
    const float* __restrict__ x, const float* __restrict__ grid,
    const float* __restrict__ dW1, const float* __restrict__ db1,
    const float* __restrict__ dW2, const float* __restrict__ db2,
    const float* __restrict__ dW3, const float* __restrict__ db3,
    const float* __restrict__ rW1, const float* __restrict__ rb1,
    const float* __restrict__ rW2, const float* __restrict__ rb2,
    const float* __restrict__ rW3, const float* __restrict__ rb3,
    float* __restrict__ out) {
    extern __shared__ uint32_t smu[];
    float* smf = (float*)smu;
    const int tid = threadIdx.x;

    // ---- one-time staging: W2 as packed fp16, pc16+swizzle layout ----
    for (int i = tid; i < 8192; i += THREADS) {
        int n = i >> 6, j = i & 63;
        int off = n * RW2 + physu(j, n & 1);
        smu[U_DW2T + off] = packh2(dW2[(2 * j) * 128 + n], dW2[(2 * j + 1) * 128 + n]);
        smu[U_RW2T + off] = packh2(rW2[(2 * j) * 128 + n], rW2[(2 * j + 1) * 128 + n]);
    }
    for (int i = tid; i < 2048; i += THREADS) smu[U_RF + i] = 0u;  // zero rf (pads)
    if (tid < 128) {
        smf[F_DB1 + tid] = db1[tid];
        smf[F_DB2 + tid] = db2[tid];
        smf[F_RB1 + tid] = rb1[tid];
        smf[F_RB2 + tid] = rb2[tid];
        smf[F_DW3 + tid] = dW3[tid];
        smf[F_RW3 + 0 * 128 + tid] = rW3[tid * 3 + 0];
        smf[F_RW3 + 1 * 128 + tid] = rW3[tid * 3 + 1];
        smf[F_RW3 + 2 * 128 + tid] = rW3[tid * 3 + 2];
    }
    if (tid == 0) smf[F_DB3] = db3[0];
    if (tid < 3) smf[F_RB3 + tid] = rb3[tid];
    __syncthreads();

    const int lane = tid & 31, warp = tid >> 5;
    const int chain = warp >> 3;
    const int cw = warp & 7;
    const int mi = cw & 1, ni = cw >> 1;
    const int m0 = mi * 32, n0 = ni * 32;
    const int r = lane >> 2, q = lane & 3;
    const int rp = r & 1;
    const int tloc = tid & 255;

    if (chain == 0) {
        // ======== DENSITY (warps 0-7) ========
        uint32_t wbd[4][2];   // persistent L1 weight fragments (K=16, 12 real)
#pragma unroll
        for (int f = 0; f < 4; f++) {
            int n = n0 + f * 8 + r;
            wbd[f][0] = packh2(dW1[(2 * q) * 128 + n], dW1[(2 * q + 1) * 128 + n]);
            float lo = (2 * q + 8 < 12) ? dW1[(2 * q + 8) * 128 + n] : 0.f;
            float hi = (2 * q + 9 < 12) ? dW1[(2 * q + 9) * 128 + n] : 0.f;
            wbd[f][1] = packh2(lo, hi);
        }

        for (int tile = blockIdx.x; tile < NTILES; tile += gridDim.x) {
            const int base = tile * TILE;
            featurize(smu, x, grid, base, tid);
            __syncthreads();

            float c[2][4][4];
#pragma unroll
            for (int mb = 0; mb < 2; mb++)
#pragma unroll
                for (int f = 0; f < 4; f++)
                    c[mb][f][0] = c[mb][f][1] = c[mb][f][2] = c[mb][f][3] = 0.f;

            // ---- L1: rf(K16) x dW1 ----
#pragma unroll
            for (int mb = 0; mb < 2; mb++) {
                int ab = U_RF + (m0 + mb * 16 + r) * RRF + (rp << 4) + 4 * q;
                uint2 lo = *(const uint2*)(smu + ab);
                uint2 hi = *(const uint2*)(smu + ab + 8 * RRF);
#pragma unroll
                for (int f = 0; f < 4; f++)
                    mma16(c[mb][f], lo.x, hi.x, lo.y, hi.y, wbd[f][0], wbd[f][1]);
            }
            // epilogue -> HD (packed fp16, one STS.128 per row)
#pragma unroll
            for (int mb = 0; mb < 2; mb++) {
                uint32_t p0[4], p1[4];
#pragma unroll
                for (int f = 0; f < 4; f++) {
                    int lc = n0 + f * 8 + 2 * q;
                    float2 b = *(const float2*)(smf + F_DB1 + lc);
                    p0[f] = packh2(fmaxf(c[mb][f][0] + b.x, 0.f),
                                   fmaxf(c[mb][f][1] + b.y, 0.f));
                    p1[f] = packh2(fmaxf(c[mb][f][2] + b.x, 0.f),
                                   fmaxf(c[mb][f][3] + b.y, 0.f));
                }
                int hb = U_HD + (m0 + mb * 16 + r) * RW2 + ((ni ^ rp) << 4) + 4 * q;
                *(uint4*)(smu + hb) = make_uint4(p0[0], p0[1], p0[2], p0[3]);
                *(uint4*)(smu + hb + 8 * RW2) = make_uint4(p1[0], p1[1], p1[2], p1[3]);
            }
            BARC(1);

            // ---- L2: HD(K128) x dW2 ----
#pragma unroll
            for (int mb = 0; mb < 2; mb++)
#pragma unroll
                for (int f = 0; f < 4; f++)
                    c[mb][f][0] = c[mb][f][1] = c[mb][f][2] = c[mb][f][3] = 0.f;
#pragma unroll
            for (int g = 0; g < 4; g++) {
                uint4 bv[4];
#pragma unroll
                for (int f = 0; f < 4; f++)
                    bv[f] = *(const uint4*)(smu + U_DW2T + (n0 + f * 8 + r) * RW2 +
                                            ((g ^ rp) << 4) + 4 * q);
                uint4 aL[2], aH[2];
#pragma unroll
                for (int mb = 0; mb < 2; mb++) {
                    int ab = U_HD + (m0 + mb * 16 + r) * RW2 + ((g ^ rp) << 4) + 4 * q;
                    aL[mb] = *(const uint4*)(smu + ab);
                    aH[mb] = *(const uint4*)(smu + ab + 8 * RW2);
                }
#pragma unroll
                for (int f = 0; f < 4; f++)
#pragma unroll
                    for (int mb = 0; mb < 2; mb++) {
                        mma16(c[mb][f], aL[mb].x, aH[mb].x, aL[mb].y, aH[mb].y,
                              bv[f].x, bv[f].y);
                        mma16(c[mb][f], aL[mb].z, aH[mb].z, aL[mb].w, aH[mb].w,
                              bv[f].z, bv[f].w);
                    }
            }
            // fused sdf head
            float ps[2][2] = {{0.f, 0.f}, {0.f, 0.f}};
#pragma unroll
            for (int f = 0; f < 4; f++) {
                int lc = n0 + f * 8 + 2 * q;
                float2 b2 = *(const float2*)(smf + F_DB2 + lc);
                float2 w3 = *(const float2*)(smf + F_DW3 + lc);
#pragma unroll
                for (int mb = 0; mb < 2; mb++) {
                    ps[mb][0] = fmaf(fmaxf(c[mb][f][0] + b2.x, 0.f), w3.x,
                                fmaf(fmaxf(c[mb][f][1] + b2.y, 0.f), w3.y, ps[mb][0]));
                    ps[mb][1] = fmaf(fmaxf(c[mb][f][2] + b2.x, 0.f), w3.x,
                                fmaf(fmaxf(c[mb][f][3] + b2.y, 0.f), w3.y, ps[mb][1]));
                }
            }
#pragma unroll
            for (int mb = 0; mb < 2; mb++)
#pragma unroll
                for (int hh = 0; hh < 2; hh++) {
                    ps[mb][hh] += __shfl_xor_sync(0xffffffffu, ps[mb][hh], 1);
                    ps[mb][hh] += __shfl_xor_sync(0xffffffffu, ps[mb][hh], 2);
                }
            if (q == 0) {
#pragma unroll
                for (int mb = 0; mb < 2; mb++) {
                    smf[F_PD + ni * 64 + m0 + mb * 16 + r]     = ps[mb][0];
                    smf[F_PD + ni * 64 + m0 + mb * 16 + r + 8] = ps[mb][1];
                }
            }
            BARC(1);
            if (tloc < 64)
                out[(size_t)(base + tloc) * 4 + 3] =
                    smf[F_PD + tloc] + smf[F_PD + 64 + tloc] +
                    smf[F_PD + 128 + tloc] + smf[F_PD + 192 + tloc] + smf[F_DB3];
            __syncthreads();
        }
    } else {
        // ======== RGB (warps 8-15) ========
        uint32_t wbr[3][4][2];  // persistent L1 fragments (K=48 real of 64)
#pragma unroll
        for (int s = 0; s < 3; s++)
#pragma unroll
            for (int f = 0; f < 4; f++) {
                int n = n0 + f * 8 + r;
                int k0 = 16 * s + 2 * q;
                float l0 = (k0 < 41) ? rW1[k0 * 128 + n] : 0.f;
                float h0 = (k0 + 1 < 41) ? rW1[(k0 + 1) * 128 + n] : 0.f;
                wbr[s][f][0] = packh2(l0, h0);
                int k1 = k0 + 8;
                float l1 = (k1 < 41) ? rW1[k1 * 128 + n] : 0.f;
                float h1 = (k1 + 1 < 41) ? rW1[(k1 + 1) * 128 + n] : 0.f;
                wbr[s][f][1] = packh2(l1, h1);
            }

        for (int tile = blockIdx.x; tile < NTILES; tile += gridDim.x) {
            const int base = tile * TILE;
            featurize(smu, x, grid, base, tid);
            __syncthreads();

            float c[2][4][4];
#pragma unroll
            for (int mb = 0; mb < 2; mb++)
#pragma unroll
                for (int f = 0; f < 4; f++)
                    c[mb][f][0] = c[mb][f][1] = c[mb][f][2] = c[mb][f][3] = 0.f;

            // ---- L1: rf(K48 of 64) x rW1 ----
#pragma unroll
            for (int g = 0; g < 2; g++) {
                uint4 aL[2], aH[2];
#pragma unroll
                for (int mb = 0; mb < 2; mb++) {
                    int ab = U_RF + (m0 + mb * 16 + r) * RRF + ((g ^ rp) << 4) + 4 * q;
                    aL[mb] = *(const uint4*)(smu + ab);
                    aH[mb] = *(const uint4*)(smu + ab + 8 * RRF);
                }
#pragma unroll
                for (int f = 0; f < 4; f++)
#pragma unroll
                    for (int mb = 0; mb < 2; mb++) {
                        mma16(c[mb][f], aL[mb].x, aH[mb].x, aL[mb].y, aH[mb].y,
                              wbr[2 * g][f][0], wbr[2 * g][f][1]);
                        if (g == 0)
                            mma16(c[mb][f], aL[mb].z, aH[mb].z, aL[mb].w, aH[mb].w,
                                  wbr[1][f][0], wbr[1][f][1]);
                    }
            }
            // epilogue -> HR
#pragma unroll
            for (int mb = 0; mb < 2; mb++) {
                uint32_t p0[4], p1[4];
#pragma unroll
                for (int f = 0; f < 4; f++) {
                    int lc = n0 + f * 8 + 2 * q;
                    float2 b = *(const float2*)(smf + F_RB1 + lc);
                    p0[f] = packh2(fmaxf(c[mb][f][0] + b.x, 0.f),
                                   fmaxf(c[mb][f][1] + b.y, 0.f));
                    p1[f] = packh2(fmaxf(c[mb][f][2] + b.x, 0.f),
                                   fmaxf(c[mb][f][3] + b.y, 0.f));
                }
                int hb = U_HR + (m0 + mb * 16 + r) * RW2 + ((ni ^ rp) << 4) + 4 * q;
                *(uint4*)(smu + hb) = make_uint4(p0[0], p0[1], p0[2], p0[3]);
                *(uint4*)(smu + hb + 8 * RW2) = make_uint4(p1[0], p1[1], p1[2], p1[3]);
            }
            BARC(2);

            // ---- L2: HR(K128) x rW2 ----
#pragma unroll
            for (int mb = 0; mb < 2; mb++)
#pragma unroll
                for (int f = 0; f < 4; f++)
                    c[mb][f][0] = c[mb][f][1] = c[mb][f][2] = c[mb][f][3] = 0.f;
#pragma unroll
            for (int g = 0; g < 4; g++) {
                uint4 bv[4];
#pragma unroll
                for (int f = 0; f < 4; f++)
                    bv[f] = *(const uint4*)(smu + U_RW2T + (n0 + f * 8 + r) * RW2 +
                                            ((g ^ rp) << 4) + 4 * q);
                uint4 aL[2], aH[2];
#pragma unroll
                for (int mb = 0; mb < 2; mb++) {
                    int ab = U_HR + (m0 + mb * 16 + r) * RW2 + ((g ^ rp) << 4) + 4 * q;
                    aL[mb] = *(const uint4*)(smu + ab);
                    aH[mb] = *(const uint4*)(smu + ab + 8 * RW2);
                }
#pragma unroll
                for (int f = 0; f < 4; f++)
#pragma unroll
                    for (int mb = 0; mb < 2; mb++) {
                        mma16(c[mb][f], aL[mb].x, aH[mb].x, aL[mb].y, aH[mb].y,
                              bv[f].x, bv[f].y);
                        mma16(c[mb][f], aL[mb].z, aH[mb].z, aL[mb].w, aH[mb].w,
                              bv[f].z, bv[f].w);
                    }
            }
            // fused rgb head
            float pc[3][2][2];
#pragma unroll
            for (int ch = 0; ch < 3; ch++)
#pragma unroll
                for (int mb = 0; mb < 2; mb++)
                    pc[ch][mb][0] = pc[ch][mb][1] = 0.f;
#pragma unroll
            for (int f = 0; f < 4; f++) {
                int lc = n0 + f * 8 + 2 * q;
                float2 b2 = *(const float2*)(smf + F_RB2 + lc);
#pragma unroll
                for (int mb = 0; mb < 2; mb++) {
                    float h0 = fmaxf(c[mb][f][0] + b2.x, 0.f);
                    float h1 = fmaxf(c[mb][f][1] + b2.y, 0.f);
                    float h2 = fmaxf(c[mb][f][2] + b2.x, 0.f);
                    float h3 = fmaxf(c[mb][f][3] + b2.y, 0.f);
#pragma unroll
                    for (int ch = 0; ch < 3; ch++) {
                        float2 w3 = *(const float2*)(smf + F_RW3 + ch * 128 + lc);
                        pc[ch][mb][0] = fmaf(h0, w3.x, fmaf(h1, w3.y, pc[ch][mb][0]));
                        pc[ch][mb][1] = fmaf(h2, w3.x, fmaf(h3, w3.y, pc[ch][mb][1]));
                    }
                }
            }
#pragma unroll
            for (int ch = 0; ch < 3; ch++)
#pragma unroll
                for (int mb = 0; mb < 2; mb++)
#pragma unroll
                    for (int hh = 0; hh < 2; hh++) {
                        pc[ch][mb][hh] += __shfl_xor_sync(0xffffffffu, pc[ch][mb][hh], 1);
                        pc[ch][mb][hh] += __shfl_xor_sync(0xffffffffu, pc[ch][mb][hh], 2);
                    }
            if (q == 0) {
#pragma unroll
                for (int ch = 0; ch < 3; ch++)
#pragma unroll
                    for (int mb = 0; mb < 2; mb++) {
                        smf[F_PR + ch * 256 + ni * 64 + m0 + mb * 16 + r]     = pc[ch][mb][0];
                        smf[F_PR + ch * 256 + ni * 64 + m0 + mb * 16 + r + 8] = pc[ch][mb][1];
                    }
            }
            BARC(2);
            if (tloc < 64) {
#pragma unroll
                for (int ch = 0; ch < 3; ch++)
                    out[(size_t)(base + tloc) * 4 + ch] =
                        smf[F_PR + ch * 256 + tloc] + smf[F_PR + ch * 256 + 64 + tloc] +
                        smf[F_PR + ch * 256 + 128 + tloc] + smf[F_PR + ch * 256 + 192 + tloc] +
                        smf[F_RB3 + ch];
            }
            __syncthreads();
        }
    }
}

extern "C" void kernel_launch(void* const* d_in, const int* in_sizes, int n_in,
                              void* d_out, int out_size) {
    (void)in_sizes; (void)n_in; (void)out_size;
    const float* x    = (const float*)d_in[0];
    const float* grid = (const float*)d_in[1];
    const float* dW1  = (const float*)d_in[2];
    const float* db1  = (const float*)d_in[3];
    const float* dW2  = (const float*)d_in[4];
    const float* db2  = (const float*)d_in[5];
    const float* dW3  = (const float*)d_in[6];
    const float* db3  = (const float*)d_in[7];
    const float* rW1  = (const float*)d_in[8];
    const float* rb1  = (const float*)d_in[9];
    const float* rW2  = (const float*)d_in[10];
    const float* rb2  = (const float*)d_in[11];
    const float* rW3  = (const float*)d_in[12];
    const float* rb3  = (const float*)d_in[13];
    float* out = (float*)d_out;

    int nsm = 148;
    cudaDeviceGetAttribute(&nsm, cudaDevAttrMultiProcessorCount, 0);
    cudaFuncSetAttribute(fastsurf_h16,
                         cudaFuncAttributeMaxDynamicSharedMemorySize, SMEM_BYTES);
    fastsurf_h16<<<nsm, THREADS, SMEM_BYTES>>>(x, grid, dW1, db1, dW2, db2, dW3, db3,
                                               rW1, rb1, rW2, rb2, rW3, rb3, out);
}

// round 15
// speedup vs baseline: 1.9744x; 1.1454x over previous
#include <cuda_runtime.h>
#include <cuda_fp16.h>
#include <math.h>
#include <stdint.h>

#define NPTS   (1 << 20)
#define RESG   160
#define TILE   64
#define NTILES (NPTS / TILE)
#define THREADS 512

#define RW2 64   // u32 per row for W2/h (K=128 halves = 64 u32)
#define RRF 32   // u32 per row for rf  (K=64 halves = 32 u32)

// ---- u32 offsets in shared ----
#define U_DW2T 0
#define U_RW2T 8192
#define U_HD   16384
#define U_HR   20480
#define U_RF0  24576
#define U_RF1  26624
#define F_DB1  28672
#define F_DB2  (F_DB1 + 128)
#define F_RB1  (F_DB2 + 128)
#define F_RB2  (F_RB1 + 128)
#define F_DW3  (F_RB2 + 128)
#define F_RW3  (F_DW3 + 128)    // [3][128]
#define F_DB3  (F_RW3 + 384)
#define F_RB3  (F_DB3 + 1)      // 3
#define F_PD   (F_RB3 + 3)      // [4][64]
#define F_PR   (F_PD + 256)     // [3][4][64]
#define SMEM_U32   (F_PR + 768)
#define SMEM_BYTES (SMEM_U32 * 4)

#define BARC(id) asm volatile("bar.sync %0, 256;" :: "r"(id) : "memory")

// physical u32 slot within a row: 16-u32 groups, pc16 interleave + row-parity xor
__device__ __forceinline__ int physu(int j, int par) {
    return (((j >> 4) ^ par) << 4) | ((j & 3) << 2) | ((j >> 2) & 3);
}

__device__ __forceinline__ uint32_t packh2(float lo, float hi) {
    __half2 h = __floats2half2_rn(lo, hi);
    return *(uint32_t*)&h;
}

__device__ __forceinline__ void mma16(float c[4], uint32_t a0, uint32_t a1,
                                      uint32_t a2, uint32_t a3,
                                      uint32_t b0, uint32_t b1) {
    asm volatile(
        "mma.sync.aligned.m16n8k16.row.col.f32.f16.f16.f32 "
        "{%0,%1,%2,%3}, {%4,%5,%6,%7}, {%8,%9}, {%0,%1,%2,%3};"
        : "+f"(c[0]), "+f"(c[1]), "+f"(c[2]), "+f"(c[3])
        : "r"(a0), "r"(a1), "r"(a2), "r"(a3), "r"(b0), "r"(b1));
}

// ---- stage A: compute corner addr, issue grid loads into registers ----
__device__ __forceinline__ void gatherA(const float* __restrict__ x,
                                        const float* __restrict__ grid,
                                        int base, int tid, bool valid,
                                        float g[12], float& wgt) {
    if (!valid) {
        wgt = 0.f;
#pragma unroll
        for (int c = 0; c < 12; c++) g[c] = 0.f;
        return;
    }
    const int p = tid >> 3, corner = tid & 7;
    const float* xp = x + (size_t)(base + p) * 8;
    float px = fminf(fmaxf(xp[0], 0.f), 1.f);
    float py = fminf(fmaxf(xp[1], 0.f), 1.f);
    float pz = fminf(fmaxf(xp[2], 0.f), 1.f);
    float fx = px * 159.f, fy = py * 159.f, fz = pz * 159.f;
    float x0f = fminf(floorf(fx), 158.f);
    float y0f = fminf(floorf(fy), 158.f);
    float z0f = fminf(floorf(fz), 158.f);
    float wx = fx - x0f, wy = fy - y0f, wz = fz - z0f;
    int xi = (int)x0f + ((corner >> 2) & 1);
    int yi = (int)y0f + ((corner >> 1) & 1);
    int zi = (int)z0f + (corner & 1);
    wgt = ((corner & 4) ? wx : 1.f - wx) *
          ((corner & 2) ? wy : 1.f - wy) *
          ((corner & 1) ? wz : 1.f - wz);
    const float* gp = grid + (size_t)((xi * RESG + yi) * RESG + zi) * 12;
    float4 g0 = *(const float4*)gp;
    float4 g1 = *(const float4*)(gp + 4);
    float4 g2 = *(const float4*)(gp + 8);
    g[0] = g0.x; g[1] = g0.y; g[2] = g0.z; g[3] = g0.w;
    g[4] = g1.x; g[5] = g1.y; g[6] = g1.z; g[7] = g1.w;
    g[8] = g2.x; g[9] = g2.y; g[10] = g2.z; g[11] = g2.w;
}

// ---- stage B: weight, shuffle-reduce, store to rf buffer ----
__device__ __forceinline__ void gatherB(uint32_t* __restrict__ smu, int rfbase,
                                        const float* __restrict__ x,
                                        int base, int tid, bool valid,
                                        const float g[12], float wgt) {
    float gv[12];
#pragma unroll
    for (int c = 0; c < 12; c++) gv[c] = g[c] * wgt;
#pragma unroll
    for (int off = 4; off; off >>= 1)
#pragma unroll
        for (int c = 0; c < 12; c++)
            gv[c] += __shfl_down_sync(0xffffffffu, gv[c], off);
    if (!valid) return;
    const int p = tid >> 3, corner = tid & 7;
    const float* xp = x + (size_t)(base + p) * 8;   // L1-hit reload
    __half* hsm = (__half*)smu;
    const int par = p & 1;
#define STH(kk, vv) do { int j_ = (kk) >> 1; \
        hsm[(rfbase + p * RRF + physu(j_, par)) * 2 + ((kk) & 1)] = __float2half_rn(vv); } while (0)
    if (corner == 0) {
#pragma unroll
        for (int c = 0; c < 12; c++) STH(c, gv[c]);
    } else if (corner <= 3) {
        int d = corner - 1;
        float vv = xp[5 + d];
        STH(12 + d, vv);
        float f = 1.f;
#pragma unroll
        for (int m = 0; m < 4; m++) {
            STH(15 + 6 * m + d, __sinf(vv * f));
            STH(15 + 6 * m + 3 + d, __cosf(vv * f));
            f *= 2.f;
        }
    } else if (corner == 4) {
        STH(39, xp[3]);
        STH(40, xp[4]);
    }
#undef STH
}

__global__ void __launch_bounds__(THREADS, 1) fastsurf_h16p(
    const float* __restrict__ x, const float* __restrict__ grid,
    const float* __restrict__ dW1, const float* __restrict__ db1,
    const float* __restrict__ dW2, const float* __restrict__ db2,
    const float* __restrict__ dW3, const float* __restrict__ db3,
    const float* __restrict__ rW1, const float* __restrict__ rb1,
    const float* __restrict__ rW2, const float* __restrict__ rb2,
    const float* __restrict__ rW3, const float* __restrict__ rb3,
    float* __restrict__ out) {
    extern __shared__ uint32_t smu[];
    float* smf = (float*)smu;
    const int tid = threadIdx.x;

    // ---- one-time staging ----
    for (int i = tid; i < 8192; i += THREADS) {
        int n = i >> 6, j = i & 63;
        int off = n * RW2 + physu(j, n & 1);
        smu[U_DW2T + off] = packh2(dW2[(2 * j) * 128 + n], dW2[(2 * j + 1) * 128 + n]);
        smu[U_RW2T + off] = packh2(rW2[(2 * j) * 128 + n], rW2[(2 * j + 1) * 128 + n]);
    }
    for (int i = tid; i < 4096; i += THREADS) smu[U_RF0 + i] = 0u;  // both rf bufs
    if (tid < 128) {
        smf[F_DB1 + tid] = db1[tid];
        smf[F_DB2 + tid] = db2[tid];
        smf[F_RB1 + tid] = rb1[tid];
        smf[F_RB2 + tid] = rb2[tid];
        smf[F_DW3 + tid] = dW3[tid];
        smf[F_RW3 + 0 * 128 + tid] = rW3[tid * 3 + 0];
        smf[F_RW3 + 1 * 128 + tid] = rW3[tid * 3 + 1];
        smf[F_RW3 + 2 * 128 + tid] = rW3[tid * 3 + 2];
    }
    if (tid == 0) smf[F_DB3] = db3[0];
    if (tid < 3) smf[F_RB3 + tid] = rb3[tid];
    __syncthreads();

    const int lane = tid & 31, warp = tid >> 5;
    const int chain = warp >> 3;
    const int cw = warp & 7;
    const int mi = cw & 1, ni = cw >> 1;
    const int m0 = mi * 32, n0 = ni * 32;
    const int r = lane >> 2, q = lane & 3;
    const int rp = r & 1;
    const int tloc = tid & 255;

    // ---- prologue: gather tile0 into rf0 ----
    {
        int t0 = blockIdx.x;
        bool v = t0 < NTILES;
        float g[12], wgt;
        gatherA(x, grid, t0 * TILE, tid, v, g, wgt);
        gatherB(smu, U_RF0, x, t0 * TILE, tid, v, g, wgt);
    }
    __syncthreads();
    int cur = 0;

    if (chain == 0) {
        // ======== DENSITY (warps 0-7) ========
        uint32_t wbd[4][2];
#pragma unroll
        for (int f = 0; f < 4; f++) {
            int n = n0 + f * 8 + r;
            wbd[f][0] = packh2(dW1[(2 * q) * 128 + n], dW1[(2 * q + 1) * 128 + n]);
            float lo = (2 * q + 8 < 12) ? dW1[(2 * q + 8) * 128 + n] : 0.f;
            float hi = (2 * q + 9 < 12) ? dW1[(2 * q + 9) * 128 + n] : 0.f;
            wbd[f][1] = packh2(lo, hi);
        }

        for (int tile = blockIdx.x; tile < NTILES; tile += gridDim.x) {
            const int base = tile * TILE;
            const int nxt = tile + gridDim.x;
            const bool vn = nxt < NTILES;
            float g[12], wgt;
            gatherA(x, grid, nxt * TILE, tid, vn, g, wgt);   // loads in flight

            const int rfb = cur ? U_RF1 : U_RF0;
            float c[2][4][4];
#pragma unroll
            for (int mb = 0; mb < 2; mb++)
#pragma unroll
                for (int f = 0; f < 4; f++)
                    c[mb][f][0] = c[mb][f][1] = c[mb][f][2] = c[mb][f][3] = 0.f;

            // ---- L1: rf(K16) x dW1 ----
#pragma unroll
            for (int mb = 0; mb < 2; mb++) {
                int ab = rfb + (m0 + mb * 16 + r) * RRF + (rp << 4) + 4 * q;
                uint2 lo = *(const uint2*)(smu + ab);
                uint2 hi = *(const uint2*)(smu + ab + 8 * RRF);
#pragma unroll
                for (int f = 0; f < 4; f++)
                    mma16(c[mb][f], lo.x, hi.x, lo.y, hi.y, wbd[f][0], wbd[f][1]);
            }
#pragma unroll
            for (int mb = 0; mb < 2; mb++) {
                uint32_t p0[4], p1[4];
#pragma unroll
                for (int f = 0; f < 4; f++) {
                    int lc = n0 + f * 8 + 2 * q;
                    float2 b = *(const float2*)(smf + F_DB1 + lc);
                    p0[f] = packh2(fmaxf(c[mb][f][0] + b.x, 0.f),
                                   fmaxf(c[mb][f][1] + b.y, 0.f));
                    p1[f] = packh2(fmaxf(c[mb][f][2] + b.x, 0.f),
                                   fmaxf(c[mb][f][3] + b.y, 0.f));
                }
                int hb = U_HD + (m0 + mb * 16 + r) * RW2 + ((ni ^ rp) << 4) + 4 * q;
                *(uint4*)(smu + hb) = make_uint4(p0[0], p0[1], p0[2], p0[3]);
                *(uint4*)(smu + hb + 8 * RW2) = make_uint4(p1[0], p1[1], p1[2], p1[3]);
            }
            BARC(1);

            // ---- L2: HD(K128) x dW2 ----
#pragma unroll
            for (int mb = 0; mb < 2; mb++)
#pragma unroll
                for (int f = 0; f < 4; f++)
                    c[mb][f][0] = c[mb][f][1] = c[mb][f][2] = c[mb][f][3] = 0.f;
#pragma unroll
            for (int gg = 0; gg < 4; gg++) {
                uint4 bv[4];
#pragma unroll
                for (int f = 0; f < 4; f++)
                    bv[f] = *(const uint4*)(smu + U_DW2T + (n0 + f * 8 + r) * RW2 +
                                            ((gg ^ rp) << 4) + 4 * q);
                uint4 aL[2], aH[2];
#pragma unroll
                for (int mb = 0; mb < 2; mb++) {
                    int ab = U_HD + (m0 + mb * 16 + r) * RW2 + ((gg ^ rp) << 4) + 4 * q;
                    aL[mb] = *(const uint4*)(smu + ab);
                    aH[mb] = *(const uint4*)(smu + ab + 8 * RW2);
                }
#pragma unroll
                for (int f = 0; f < 4; f++)
#pragma unroll
                    for (int mb = 0; mb < 2; mb++) {
                        mma16(c[mb][f], aL[mb].x, aH[mb].x, aL[mb].y, aH[mb].y,
                              bv[f].x, bv[f].y);
                        mma16(c[mb][f], aL[mb].z, aH[mb].z, aL[mb].w, aH[mb].w,
                              bv[f].z, bv[f].w);
                    }
            }
            // fused sdf head
            float ps[2][2] = {{0.f, 0.f}, {0.f, 0.f}};
#pragma unroll
            for (int f = 0; f < 4; f++) {
                int lc = n0 + f * 8 + 2 * q;
                float2 b2 = *(const float2*)(smf + F_DB2 + lc);
                float2 w3 = *(const float2*)(smf + F_DW3 + lc);
#pragma unroll
                for (int mb = 0; mb < 2; mb++) {
                    ps[mb][0] = fmaf(fmaxf(c[mb][f][0] + b2.x, 0.f), w3.x,
                                fmaf(fmaxf(c[mb][f][1] + b2.y, 0.f), w3.y, ps[mb][0]));
                    ps[mb][1] = fmaf(fmaxf(c[mb][f][2] + b2.x, 0.f), w3.x,
                                fmaf(fmaxf(c[mb][f][3] + b2.y, 0.f), w3.y, ps[mb][1]));
                }
            }
#pragma unroll
            for (int mb = 0; mb < 2; mb++)
#pragma unroll
                for (int hh = 0; hh < 2; hh++) {
                    ps[mb][hh] += __shfl_xor_sync(0xffffffffu, ps[mb][hh], 1);
                    ps[mb][hh] += __shfl_xor_sync(0xffffffffu, ps[mb][hh], 2);
                }
            if (q == 0) {
#pragma unroll
                for (int mb = 0; mb < 2; mb++) {
                    smf[F_PD + ni * 64 + m0 + mb * 16 + r]     = ps[mb][0];
                    smf[F_PD + ni * 64 + m0 + mb * 16 + r + 8] = ps[mb][1];
                }
            }
            BARC(1);
            if (tloc < 64)
                out[(size_t)(base + tloc) * 4 + 3] =
                    smf[F_PD + tloc] + smf[F_PD + 64 + tloc] +
                    smf[F_PD + 128 + tloc] + smf[F_PD + 192 + tloc] + smf[F_DB3];
            gatherB(smu, cur ? U_RF0 : U_RF1, x, nxt * TILE, tid, vn, g, wgt);
            __syncthreads();
            cur ^= 1;
        }
    } else {
        // ======== RGB (warps 8-15) ========
        uint32_t wbr[3][4][2];
#pragma unroll
        for (int s = 0; s < 3; s++)
#pragma unroll
            for (int f = 0; f < 4; f++) {
                int n = n0 + f * 8 + r;
                int k0 = 16 * s + 2 * q;
                float l0 = (k0 < 41) ? rW1[k0 * 128 + n] : 0.f;
                float h0 = (k0 + 1 < 41) ? rW1[(k0 + 1) * 128 + n] : 0.f;
                wbr[s][f][0] = packh2(l0, h0);
                int k1 = k0 + 8;
                float l1 = (k1 < 41) ? rW1[k1 * 128 + n] : 0.f;
                float h1 = (k1 + 1 < 41) ? rW1[(k1 + 1) * 128 + n] : 0.f;
                wbr[s][f][1] = packh2(l1, h1);
            }

        for (int tile = blockIdx.x; tile < NTILES; tile += gridDim.x) {
            const int base = tile * TILE;
            const int nxt = tile + gridDim.x;
            const bool vn = nxt < NTILES;
            float g[12], wgt;
            gatherA(x, grid, nxt * TILE, tid, vn, g, wgt);

            const int rfb = cur ? U_RF1 : U_RF0;
            float c[2][4][4];
#pragma unroll
            for (int mb = 0; mb < 2; mb++)
#pragma unroll
                for (int f = 0; f < 4; f++)
                    c[mb][f][0] = c[mb][f][1] = c[mb][f][2] = c[mb][f][3] = 0.f;

            // ---- L1: rf(K48 of 64) x rW1 ----
#pragma unroll
            for (int gg = 0; gg < 2; gg++) {
                uint4 aL[2], aH[2];
#pragma unroll
                for (int mb = 0; mb < 2; mb++) {
                    int ab = rfb + (m0 + mb * 16 + r) * RRF + ((gg ^ rp) << 4) + 4 * q;
                    aL[mb] = *(const uint4*)(smu + ab);
                    aH[mb] = *(const uint4*)(smu + ab + 8 * RRF);
                }
#pragma unroll
                for (int f = 0; f < 4; f++)
#pragma unroll
                    for (int mb = 0; mb < 2; mb++) {
                        mma16(c[mb][f], aL[mb].x, aH[mb].x, aL[mb].y, aH[mb].y,
                              wbr[2 * gg][f][0], wbr[2 * gg][f][1]);
                        if (gg == 0)
                            mma16(c[mb][f], aL[mb].z, aH[mb].z, aL[mb].w, aH[mb].w,
                                  wbr[1][f][0], wbr[1][f][1]);
                    }
            }
#pragma unroll
            for (int mb = 0; mb < 2; mb++) {
                uint32_t p0[4], p1[4];
#pragma unroll
                for (int f = 0; f < 4; f++) {
                    int lc = n0 + f * 8 + 2 * q;
                    float2 b = *(const float2*)(smf + F_RB1 + lc);
                    p0[f] = packh2(fmaxf(c[mb][f][0] + b.x, 0.f),
                                   fmaxf(c[mb][f][1] + b.y, 0.f));
                    p1[f] = packh2(fmaxf(c[mb][f][2] + b.x, 0.f),
                                   fmaxf(c[mb][f][3] + b.y, 0.f));
                }
                int hb = U_HR + (m0 + mb * 16 + r) * RW2 + ((ni ^ rp) << 4) + 4 * q;
                *(uint4*)(smu + hb) = make_uint4(p0[0], p0[1], p0[2], p0[3]);
                *(uint4*)(smu + hb + 8 * RW2) = make_uint4(p1[0], p1[1], p1[2], p1[3]);
            }
            BARC(2);

            // ---- L2: HR(K128) x rW2 ----
#pragma unroll
            for (int mb = 0; mb < 2; mb++)
#pragma unroll
                for (int f = 0; f < 4; f++)
                    c[mb][f][0] = c[mb][f][1] = c[mb][f][2] = c[mb][f][3] = 0.f;
#pragma unroll
            for (int gg = 0; gg < 4; gg++) {
                uint4 bv[4];
#pragma unroll
                for (int f = 0; f < 4; f++)
                    bv[f] = *(const uint4*)(smu + U_RW2T + (n0 + f * 8 + r) * RW2 +
                                            ((gg ^ rp) << 4) + 4 * q);
                uint4 aL[2], aH[2];
#pragma unroll
                for (int mb = 0; mb < 2; mb++) {
                    int ab = U_HR + (m0 + mb * 16 + r) * RW2 + ((gg ^ rp) << 4) + 4 * q;
                    aL[mb] = *(const uint4*)(smu + ab);
                    aH[mb] = *(const uint4*)(smu + ab + 8 * RW2);
                }
#pragma unroll
                for (int f = 0; f < 4; f++)
#pragma unroll
                    for (int mb = 0; mb < 2; mb++) {
                        mma16(c[mb][f], aL[mb].x, aH[mb].x, aL[mb].y, aH[mb].y,
                              bv[f].x, bv[f].y);
                        mma16(c[mb][f], aL[mb].z, aH[mb].z, aL[mb].w, aH[mb].w,
                              bv[f].z, bv[f].w);
                    }
            }
            // fused rgb head
            float pc[3][2][2];
#pragma unroll
            for (int ch = 0; ch < 3; ch++)
#pragma unroll
                for (int mb = 0; mb < 2; mb++)
                    pc[ch][mb][0] = pc[ch][mb][1] = 0.f;
#pragma unroll
            for (int f = 0; f < 4; f++) {
                int lc = n0 + f * 8 + 2 * q;
                float2 b2 = *(const float2*)(smf + F_RB2 + lc);
#pragma unroll
                for (int mb = 0; mb < 2; mb++) {
                    float h0 = fmaxf(c[mb][f][0] + b2.x, 0.f);
                    float h1 = fmaxf(c[mb][f][1] + b2.y, 0.f);
                    float h2 = fmaxf(c[mb][f][2] + b2.x, 0.f);
                    float h3 = fmaxf(c[mb][f][3] + b2.y, 0.f);
#pragma unroll
                    for (int ch = 0; ch < 3; ch++) {
                        float2 w3 = *(const float2*)(smf + F_RW3 + ch * 128 + lc);
                        pc[ch][mb][0] = fmaf(h0, w3.x, fmaf(h1, w3.y, pc[ch][mb][0]));
                        pc[ch][mb][1] = fmaf(h2, w3.x, fmaf(h3, w3.y, pc[ch][mb][1]));
                    }
                }
            }
#pragma unroll
            for (int ch = 0; ch < 3; ch++)
#pragma unroll
                for (int mb = 0; mb < 2; mb++)
#pragma unroll
                    for (int hh = 0; hh < 2; hh++) {
                        pc[ch][mb][hh] += __shfl_xor_sync(0xffffffffu, pc[ch][mb][hh], 1);
                        pc[ch][mb][hh] += __shfl_xor_sync(0xffffffffu, pc[ch][mb][hh], 2);
                    }
            if (q == 0) {
#pragma unroll
                for (int ch = 0; ch < 3; ch++)
#pragma unroll
                    for (int mb = 0; mb < 2; mb++) {
                        smf[F_PR + ch * 256 + ni * 64 + m0 + mb * 16 + r]     = pc[ch][mb][0];
                        smf[F_PR + ch * 256 + ni * 64 + m0 + mb * 16 + r + 8] = pc[ch][mb][1];
                    }
            }
            BARC(2);
            if (tloc < 64) {
#pragma unroll
                for (int ch = 0; ch < 3; ch++)
                    out[(size_t)(base + tloc) * 4 + ch] =
                        smf[F_PR + ch * 256 + tloc] + smf[F_PR + ch * 256 + 64 + tloc] +
                        smf[F_PR + ch * 256 + 128 + tloc] + smf[F_PR + ch * 256 + 192 + tloc] +
                        smf[F_RB3 + ch];
            }
            gatherB(smu, cur ? U_RF0 : U_RF1, x, nxt * TILE, tid, vn, g, wgt);
            __syncthreads();
            cur ^= 1;
        }
    }
}

extern "C" void kernel_launch(void* const* d_in, const int* in_sizes, int n_in,
                              void* d_out, int out_size) {
    (void)in_sizes; (void)n_in; (void)out_size;
    const float* x    = (const float*)d_in[0];
    const float* grid = (const float*)d_in[1];
    const float* dW1  = (const float*)d_in[2];
    const float* db1  = (const float*)d_in[3];
    const float* dW2  = (const float*)d_in[4];
    const float* db2  = (const float*)d_in[5];
    const float* dW3  = (const float*)d_in[6];
    const float* db3  = (const float*)d_in[7];
    const float* rW1  = (const float*)d_in[8];
    const float* rb1  = (const float*)d_in[9];
    const float* rW2  = (const float*)d_in[10];
    const float* rb2  = (const float*)d_in[11];
    const float* rW3  = (const float*)d_in[12];
    const float* rb3  = (const float*)d_in[13];
    float* out = (float*)d_out;

    int nsm = 148;
    cudaDeviceGetAttribute(&nsm, cudaDevAttrMultiProcessorCount, 0);
    cudaFuncSetAttribute(fastsurf_h16p,
                         cudaFuncAttributeMaxDynamicSharedMemorySize, SMEM_BYTES);
    fastsurf_h16p<<<nsm, THREADS, SMEM_BYTES>>>(x, grid, dW1, db1, dW2, db2, dW3, db3,
                                                rW1, rb1, rW2, rb2, rW3, rb3, out);
}